// round 1
// baseline (speedup 1.0000x reference)
#include <cuda_runtime.h>
#include <math.h>

#define HIDDEN 2048
#define NH 16
#define HD 128
#define BATCH 2
#define SEQ 2048
#define ROWS (BATCH*SEQ)   /* 4096 */

// Scratch (allocation-free: __device__ globals)
__device__ float g_Q[ROWS * HIDDEN];
__device__ float g_K[ROWS * HIDDEN];
__device__ float g_V[ROWS * HIDDEN];
__device__ float g_ctx[ROWS * HIDDEN];
__device__ float g_S[134217728];   /* 32 * 2048 * 2048 scores/probs */

// ---------------------------------------------------------------------------
// C[M,N] = alpha * A[M,K] @ B[N,K]^T   (both K-contiguous / row-major)
// 128x128 tile, BK=16, 256 threads, 8x8 per-thread microtile.
// Batch offset: z -> (z>>4)*s?B + (z&15)*s?H   (covers both flat and b/h split)
// ---------------------------------------------------------------------------
__global__ __launch_bounds__(256) void gemm_nt(
    const float* __restrict__ A, int lda, long long saB, long long saH,
    const float* __restrict__ B, int ldb, long long sbB, long long sbH,
    float* __restrict__ C, int ldc, long long scB, long long scH,
    int K, float alpha)
{
    __shared__ float As[16][128];
    __shared__ float Bs[16][128];

    const int z  = blockIdx.z;
    const long long zb = z >> 4, zh = z & 15;
    A += zb * saB + zh * saH + (long long)blockIdx.y * 128 * lda;
    B += zb * sbB + zh * sbH + (long long)blockIdx.x * 128 * ldb;
    C += zb * scB + zh * scH + (long long)blockIdx.y * 128 * ldc
                             + (long long)blockIdx.x * 128;

    const int tid = threadIdx.x;
    const int tx = tid & 15, ty = tid >> 4;

    float acc[8][8];
    #pragma unroll
    for (int i = 0; i < 8; i++)
        #pragma unroll
        for (int j = 0; j < 8; j++) acc[i][j] = 0.0f;

    for (int kt = 0; kt < K; kt += 16) {
        #pragma unroll
        for (int l = 0; l < 2; l++) {
            int L = tid + l * 256;
            int row = L >> 2;
            int cv  = (L & 3) * 4;
            float4 a = *(const float4*)(A + (long long)row * lda + kt + cv);
            As[cv + 0][row] = a.x; As[cv + 1][row] = a.y;
            As[cv + 2][row] = a.z; As[cv + 3][row] = a.w;
            float4 b = *(const float4*)(B + (long long)row * ldb + kt + cv);
            Bs[cv + 0][row] = b.x; Bs[cv + 1][row] = b.y;
            Bs[cv + 2][row] = b.z; Bs[cv + 3][row] = b.w;
        }
        __syncthreads();
        #pragma unroll
        for (int k = 0; k < 16; k++) {
            float a_[8], b_[8];
            *(float4*)&a_[0] = *(const float4*)&As[k][ty * 8];
            *(float4*)&a_[4] = *(const float4*)&As[k][ty * 8 + 4];
            *(float4*)&b_[0] = *(const float4*)&Bs[k][tx * 8];
            *(float4*)&b_[4] = *(const float4*)&Bs[k][tx * 8 + 4];
            #pragma unroll
            for (int i = 0; i < 8; i++)
                #pragma unroll
                for (int j = 0; j < 8; j++)
                    acc[i][j] += a_[i] * b_[j];
        }
        __syncthreads();
    }

    #pragma unroll
    for (int i = 0; i < 8; i++) {
        float4 o0, o1;
        o0.x = acc[i][0] * alpha; o0.y = acc[i][1] * alpha;
        o0.z = acc[i][2] * alpha; o0.w = acc[i][3] * alpha;
        o1.x = acc[i][4] * alpha; o1.y = acc[i][5] * alpha;
        o1.z = acc[i][6] * alpha; o1.w = acc[i][7] * alpha;
        float* cr = C + (long long)(ty * 8 + i) * ldc + tx * 8;
        *(float4*)(cr)     = o0;
        *(float4*)(cr + 4) = o1;
    }
}

// ---------------------------------------------------------------------------
// C[M,N] = A[M,K] @ B[K,N]   (A K-contiguous, B N-contiguous)  -- for P@V
// ---------------------------------------------------------------------------
__global__ __launch_bounds__(256) void gemm_nn(
    const float* __restrict__ A, int lda, long long saB, long long saH,
    const float* __restrict__ B, int ldb, long long sbB, long long sbH,
    float* __restrict__ C, int ldc, long long scB, long long scH,
    int K)
{
    __shared__ float As[16][128];
    __shared__ float Bs[16][128];

    const int z  = blockIdx.z;
    const long long zb = z >> 4, zh = z & 15;
    A += zb * saB + zh * saH + (long long)blockIdx.y * 128 * lda;
    B += zb * sbB + zh * sbH + (long long)blockIdx.x * 128;
    C += zb * scB + zh * scH + (long long)blockIdx.y * 128 * ldc
                             + (long long)blockIdx.x * 128;

    const int tid = threadIdx.x;
    const int tx = tid & 15, ty = tid >> 4;

    float acc[8][8];
    #pragma unroll
    for (int i = 0; i < 8; i++)
        #pragma unroll
        for (int j = 0; j < 8; j++) acc[i][j] = 0.0f;

    for (int kt = 0; kt < K; kt += 16) {
        #pragma unroll
        for (int l = 0; l < 2; l++) {
            int L = tid + l * 256;
            // A tile (transpose into As[k][m])
            int row = L >> 2;
            int cv  = (L & 3) * 4;
            float4 a = *(const float4*)(A + (long long)row * lda + kt + cv);
            As[cv + 0][row] = a.x; As[cv + 1][row] = a.y;
            As[cv + 2][row] = a.z; As[cv + 3][row] = a.w;
            // B tile (direct: Bs[k][n])
            int brow = L >> 5;
            int bcol = (L & 31) * 4;
            float4 b = *(const float4*)(B + (long long)(kt + brow) * ldb + bcol);
            *(float4*)&Bs[brow][bcol] = b;
        }
        __syncthreads();
        #pragma unroll
        for (int k = 0; k < 16; k++) {
            float a_[8], b_[8];
            *(float4*)&a_[0] = *(const float4*)&As[k][ty * 8];
            *(float4*)&a_[4] = *(const float4*)&As[k][ty * 8 + 4];
            *(float4*)&b_[0] = *(const float4*)&Bs[k][tx * 8];
            *(float4*)&b_[4] = *(const float4*)&Bs[k][tx * 8 + 4];
            #pragma unroll
            for (int i = 0; i < 8; i++)
                #pragma unroll
                for (int j = 0; j < 8; j++)
                    acc[i][j] += a_[i] * b_[j];
        }
        __syncthreads();
    }

    #pragma unroll
    for (int i = 0; i < 8; i++) {
        float* cr = C + (long long)(ty * 8 + i) * ldc + tx * 8;
        *(float4*)(cr)     = *(float4*)&acc[i][0];
        *(float4*)(cr + 4) = *(float4*)&acc[i][4];
    }
}

// ---------------------------------------------------------------------------
// RoPE in place on Q and K. One thread per (row, head, j<64) pair.
// inv_freq[j] = 10000^{-j/64}; rotate_half convention (LLaMA).
// ---------------------------------------------------------------------------
__global__ __launch_bounds__(256) void rope_kernel(float* __restrict__ Q,
                                                   float* __restrict__ K)
{
    int idx = blockIdx.x * blockDim.x + threadIdx.x;
    if (idx >= ROWS * NH * 64) return;
    int j   = idx & 63;
    int h   = (idx >> 6) & (NH - 1);
    int row = idx >> 10;
    int s   = row & (SEQ - 1);

    float invf = powf(10000.0f, -(float)j * (1.0f / 64.0f));
    float ang  = (float)s * invf;
    float c = cosf(ang), sn = sinf(ang);

    long long base = (long long)row * HIDDEN + h * HD + j;
    float q0 = Q[base], q1 = Q[base + 64];
    Q[base]      = q0 * c - q1 * sn;
    Q[base + 64] = q1 * c + q0 * sn;
    float k0 = K[base], k1 = K[base + 64];
    K[base]      = k0 * c - k1 * sn;
    K[base + 64] = k1 * c + k0 * sn;
}

// ---------------------------------------------------------------------------
// Row softmax in place. One block per row of length SEQ (2048). 256 threads,
// 8 elements per thread.
// ---------------------------------------------------------------------------
__global__ __launch_bounds__(256) void softmax_rows(float* __restrict__ S)
{
    __shared__ float red[8];
    long long row = blockIdx.x;
    float* p = S + row * SEQ;
    int tid = threadIdx.x;
    int lane = tid & 31, wid = tid >> 5;

    float v[8];
    float4 x0 = *(const float4*)(p + tid * 8);
    float4 x1 = *(const float4*)(p + tid * 8 + 4);
    v[0] = x0.x; v[1] = x0.y; v[2] = x0.z; v[3] = x0.w;
    v[4] = x1.x; v[5] = x1.y; v[6] = x1.z; v[7] = x1.w;

    float m = v[0];
    #pragma unroll
    for (int i = 1; i < 8; i++) m = fmaxf(m, v[i]);
    #pragma unroll
    for (int o = 16; o; o >>= 1) m = fmaxf(m, __shfl_xor_sync(0xFFFFFFFFu, m, o));
    if (lane == 0) red[wid] = m;
    __syncthreads();
    m = red[0];
    #pragma unroll
    for (int i = 1; i < 8; i++) m = fmaxf(m, red[i]);
    __syncthreads();

    float sum = 0.0f;
    #pragma unroll
    for (int i = 0; i < 8; i++) { v[i] = expf(v[i] - m); sum += v[i]; }
    #pragma unroll
    for (int o = 16; o; o >>= 1) sum += __shfl_xor_sync(0xFFFFFFFFu, sum, o);
    if (lane == 0) red[wid] = sum;
    __syncthreads();
    sum = 0.0f;
    #pragma unroll
    for (int i = 0; i < 8; i++) sum += red[i];
    float inv = 1.0f / sum;

    float4 y0, y1;
    y0.x = v[0] * inv; y0.y = v[1] * inv; y0.z = v[2] * inv; y0.w = v[3] * inv;
    y1.x = v[4] * inv; y1.y = v[5] * inv; y1.z = v[6] * inv; y1.w = v[7] * inv;
    *(float4*)(p + tid * 8)     = y0;
    *(float4*)(p + tid * 8 + 4) = y1;
}

// ---------------------------------------------------------------------------
extern "C" void kernel_launch(void* const* d_in, const int* in_sizes, int n_in,
                              void* d_out, int out_size)
{
    const float* X  = (const float*)d_in[0];
    const float* Wq = (const float*)d_in[1];
    const float* Wk = (const float*)d_in[2];
    const float* Wv = (const float*)d_in[3];
    const float* Wo = (const float*)d_in[4];
    float* out = (float*)d_out;

    float *Q, *K, *V, *CTX, *S;
    cudaGetSymbolAddress((void**)&Q,   g_Q);
    cudaGetSymbolAddress((void**)&K,   g_K);
    cudaGetSymbolAddress((void**)&V,   g_V);
    cudaGetSymbolAddress((void**)&CTX, g_ctx);
    cudaGetSymbolAddress((void**)&S,   g_S);

    const long long SH  = (long long)SEQ * HIDDEN;     // batch stride of Q/K/V/ctx
    const long long SS  = (long long)SEQ * SEQ;        // per-(b,h) scores stride
    const float scale = 0.08838834764831845f;          // 1/sqrt(128)

    dim3 blk(256);

    // QKV projections: [4096,2048] @ W^T
    dim3 gproj(HIDDEN / 128, ROWS / 128, 1);
    gemm_nt<<<gproj, blk>>>(X, HIDDEN, 0, 0, Wq, HIDDEN, 0, 0,
                            Q, HIDDEN, 0, 0, HIDDEN, 1.0f);
    gemm_nt<<<gproj, blk>>>(X, HIDDEN, 0, 0, Wk, HIDDEN, 0, 0,
                            K, HIDDEN, 0, 0, HIDDEN, 1.0f);
    gemm_nt<<<gproj, blk>>>(X, HIDDEN, 0, 0, Wv, HIDDEN, 0, 0,
                            V, HIDDEN, 0, 0, HIDDEN, 1.0f);

    // RoPE on Q and K
    rope_kernel<<<(ROWS * NH * 64) / 256, blk>>>(Q, K);

    // scores[b,h] = scale * Q_bh @ K_bh^T   (K=128), z = b*16+h
    dim3 gsc(SEQ / 128, SEQ / 128, BATCH * NH);
    gemm_nt<<<gsc, blk>>>(Q, HIDDEN, SH, HD,
                          K, HIDDEN, SH, HD,
                          S, SEQ, 16 * SS, SS,
                          HD, scale);

    // softmax rows in place
    softmax_rows<<<BATCH * NH * SEQ, blk>>>(S);

    // ctx[b,h] = P_bh @ V_bh   (M=2048, N=128, K=2048)
    dim3 gpv(HD / 128, SEQ / 128, BATCH * NH);
    gemm_nn<<<gpv, blk>>>(S, SEQ, 16 * SS, SS,
                          V, HIDDEN, SH, HD,
                          CTX, HIDDEN, SH, HD,
                          SEQ);

    // output projection: ctx @ Wo^T -> out
    gemm_nt<<<gproj, blk>>>(CTX, HIDDEN, 0, 0, Wo, HIDDEN, 0, 0,
                            out, HIDDEN, 0, 0, HIDDEN, 1.0f);
}